// round 1
// baseline (speedup 1.0000x reference)
#include <cuda_runtime.h>
#include <cuda_bf16.h>
#include <math.h>

#define SEQ 2048
#define NH  16
#define HD  80
#define DIM 1280            // NH*HD
#define QKV_N 3840          // 3*DIM
#define ATTN_SCALE 0.11180339887498949f   // 80^-0.5

// ---------------- scratch (device globals; no allocations allowed) ----------
__device__ float g_qkv[SEQ * QKV_N];          // 31.5 MB
__device__ float g_q[NH * SEQ * HD];          // 10.5 MB
__device__ float g_k[NH * SEQ * HD];
__device__ float g_v[NH * SEQ * HD];
__device__ float g_s[(size_t)NH * SEQ * SEQ]; // 256 MB scores
__device__ float g_o[SEQ * DIM];              // 10.5 MB

// ---------------- generic NT GEMM: C[b] = alpha * A[b] (MxK) * B[b](NxK)^T + bias ----
// A,B row-major with lda=ldb=K. Requires M%64==0, N%64==0, K%16==0.
__global__ __launch_bounds__(256) void gemm_nt(
    const float* __restrict__ A, const float* __restrict__ B,
    const float* __restrict__ bias, float* __restrict__ C,
    int K, size_t sA, size_t sB, size_t sC, int ldc, float alpha)
{
    __shared__ float As[16][64];
    __shared__ float Bs[16][64];

    const int b = blockIdx.z;
    const float* Ab = A + b * sA;
    const float* Bb = B + b * sB;
    float* Cb = C + b * sC;

    const int m0 = blockIdx.y * 64;
    const int n0 = blockIdx.x * 64;
    const int tid = threadIdx.x;
    const int ty = tid >> 4;      // 0..15
    const int tx = tid & 15;      // 0..15

    const int lrow = tid >> 2;        // 0..63
    const int lk4 = (tid & 3) << 2;   // 0,4,8,12

    float acc[4][4] = {};

    for (int k0 = 0; k0 < K; k0 += 16) {
        float4 av = *reinterpret_cast<const float4*>(Ab + (size_t)(m0 + lrow) * K + k0 + lk4);
        As[lk4 + 0][lrow] = av.x; As[lk4 + 1][lrow] = av.y;
        As[lk4 + 2][lrow] = av.z; As[lk4 + 3][lrow] = av.w;
        float4 bv = *reinterpret_cast<const float4*>(Bb + (size_t)(n0 + lrow) * K + k0 + lk4);
        Bs[lk4 + 0][lrow] = bv.x; Bs[lk4 + 1][lrow] = bv.y;
        Bs[lk4 + 2][lrow] = bv.z; Bs[lk4 + 3][lrow] = bv.w;
        __syncthreads();

        #pragma unroll
        for (int k = 0; k < 16; k++) {
            float4 a = *reinterpret_cast<const float4*>(&As[k][ty << 2]);
            float4 bb = *reinterpret_cast<const float4*>(&Bs[k][tx << 2]);
            float ar[4] = {a.x, a.y, a.z, a.w};
            float br[4] = {bb.x, bb.y, bb.z, bb.w};
            #pragma unroll
            for (int i = 0; i < 4; i++)
                #pragma unroll
                for (int j = 0; j < 4; j++)
                    acc[i][j] = fmaf(ar[i], br[j], acc[i][j]);
        }
        __syncthreads();
    }

    #pragma unroll
    for (int i = 0; i < 4; i++) {
        const int row = m0 + (ty << 2) + i;
        #pragma unroll
        for (int j = 0; j < 4; j++) {
            const int col = n0 + (tx << 2) + j;
            float v = acc[i][j] * alpha;
            if (bias) v += bias[col];
            Cb[(size_t)row * ldc + col] = v;
        }
    }
}

// ---------------- RoPE + split to per-head layout ---------------------------
__global__ __launch_bounds__(256) void rope_split(
    const float* __restrict__ qkv, const float* __restrict__ cosp,
    const float* __restrict__ sinp,
    float* __restrict__ Q, float* __restrict__ Kb, float* __restrict__ V)
{
    int idx = blockIdx.x * blockDim.x + threadIdx.x;
    if (idx >= SEQ * DIM) return;
    const int d = idx % HD;
    const int h = (idx / HD) % NH;
    const int s = idx / DIM;

    const float c = cosp[s * HD + d];
    const float sn = sinp[s * HD + d];
    const int d2 = (d < HD / 2) ? d + HD / 2 : d - HD / 2;
    const float sign = (d < HD / 2) ? -1.0f : 1.0f;

    const size_t rowbase = (size_t)s * QKV_N + h * HD;
    const size_t out = ((size_t)h * SEQ + s) * HD + d;

    const float qv = qkv[rowbase + d];
    const float q2 = qkv[rowbase + d2];
    Q[out] = fmaf(qv, c, sign * q2 * sn);

    const float kv = qkv[rowbase + DIM + d];
    const float k2 = qkv[rowbase + DIM + d2];
    Kb[out] = fmaf(kv, c, sign * k2 * sn);

    V[out] = qkv[rowbase + 2 * DIM + d];
}

// ---------------- row softmax over SEQ=2048 elements -------------------------
__global__ __launch_bounds__(256) void softmax_rows(float* __restrict__ S)
{
    float* row = S + (size_t)blockIdx.x * SEQ;
    const int tid = threadIdx.x;
    __shared__ float red[256];

    float v[8];
    float mx = -1e30f;
    #pragma unroll
    for (int i = 0; i < 8; i++) {
        v[i] = row[tid + i * 256];
        mx = fmaxf(mx, v[i]);
    }
    red[tid] = mx;
    __syncthreads();
    for (int s = 128; s > 0; s >>= 1) {
        if (tid < s) red[tid] = fmaxf(red[tid], red[tid + s]);
        __syncthreads();
    }
    mx = red[0];
    __syncthreads();

    float sum = 0.0f;
    #pragma unroll
    for (int i = 0; i < 8; i++) {
        v[i] = __expf(v[i] - mx);
        sum += v[i];
    }
    red[tid] = sum;
    __syncthreads();
    for (int s = 128; s > 0; s >>= 1) {
        if (tid < s) red[tid] += red[tid + s];
        __syncthreads();
    }
    const float inv = 1.0f / red[0];
    #pragma unroll
    for (int i = 0; i < 8; i++) row[tid + i * 256] = v[i] * inv;
}

// ---------------- NN GEMM: O_h[s,d] = sum_t P_h[s,t] * V_h[t,d] -------------
// BM=64, BN=80 (full head dim), BK=16. Output written into [s, h*80+d] layout.
__global__ __launch_bounds__(256) void gemm_pv(
    const float* __restrict__ P, const float* __restrict__ V,
    float* __restrict__ O)
{
    __shared__ float Ps[16][64];
    __shared__ float Vs[16][80];

    const int h = blockIdx.z;
    const float* Pb = P + (size_t)h * SEQ * SEQ;
    const float* Vb = V + (size_t)h * SEQ * HD;

    const int m0 = blockIdx.y * 64;
    const int tid = threadIdx.x;
    const int ty = tid >> 4;      // 0..15 -> rows ty*4..+3
    const int tx = tid & 15;      // 0..15 -> cols tx*5..+4

    const int lrow = tid >> 2;
    const int lk4 = (tid & 3) << 2;
    const int vkk = tid >> 4;          // 0..15
    const int vc5 = (tid & 15) * 5;    // 0..75

    float acc[4][5] = {};

    for (int k0 = 0; k0 < SEQ; k0 += 16) {
        float4 pv = *reinterpret_cast<const float4*>(Pb + (size_t)(m0 + lrow) * SEQ + k0 + lk4);
        Ps[lk4 + 0][lrow] = pv.x; Ps[lk4 + 1][lrow] = pv.y;
        Ps[lk4 + 2][lrow] = pv.z; Ps[lk4 + 3][lrow] = pv.w;
        #pragma unroll
        for (int j = 0; j < 5; j++)
            Vs[vkk][vc5 + j] = Vb[(size_t)(k0 + vkk) * HD + vc5 + j];
        __syncthreads();

        #pragma unroll
        for (int k = 0; k < 16; k++) {
            float4 a = *reinterpret_cast<const float4*>(&Ps[k][ty << 2]);
            float ar[4] = {a.x, a.y, a.z, a.w};
            float br[5];
            #pragma unroll
            for (int j = 0; j < 5; j++) br[j] = Vs[k][tx * 5 + j];
            #pragma unroll
            for (int i = 0; i < 4; i++)
                #pragma unroll
                for (int j = 0; j < 5; j++)
                    acc[i][j] = fmaf(ar[i], br[j], acc[i][j]);
        }
        __syncthreads();
    }

    #pragma unroll
    for (int i = 0; i < 4; i++) {
        const int row = m0 + (ty << 2) + i;
        #pragma unroll
        for (int j = 0; j < 5; j++) {
            const int col = h * HD + tx * 5 + j;
            O[(size_t)row * DIM + col] = acc[i][j];
        }
    }
}

// ---------------- launch -----------------------------------------------------
extern "C" void kernel_launch(void* const* d_in, const int* in_sizes, int n_in,
                              void* d_out, int out_size)
{
    const float* hidden = (const float*)d_in[0];
    // d_in[1] = cu_seqlens (unused: single sequence [0, SEQ])
    const float* cosp   = (const float*)d_in[2];
    const float* sinp   = (const float*)d_in[3];
    const float* w_qkv  = (const float*)d_in[4];
    const float* b_qkv  = (const float*)d_in[5];
    const float* w_proj = (const float*)d_in[6];
    const float* b_proj = (const float*)d_in[7];
    float* out = (float*)d_out;

    float *qkv, *Q, *K, *V, *S, *O;
    cudaGetSymbolAddress((void**)&qkv, g_qkv);
    cudaGetSymbolAddress((void**)&Q, g_q);
    cudaGetSymbolAddress((void**)&K, g_k);
    cudaGetSymbolAddress((void**)&V, g_v);
    cudaGetSymbolAddress((void**)&S, g_s);
    cudaGetSymbolAddress((void**)&O, g_o);

    // 1) QKV = hidden @ w_qkv^T + b_qkv     [2048, 3840]
    {
        dim3 grid(QKV_N / 64, SEQ / 64, 1);
        gemm_nt<<<grid, 256>>>(hidden, w_qkv, b_qkv, qkv,
                               DIM, 0, 0, 0, QKV_N, 1.0f);
    }
    // 2) RoPE + split into per-head Q,K,V  [h][s][d]
    {
        int total = SEQ * DIM;
        rope_split<<<(total + 255) / 256, 256>>>(qkv, cosp, sinp, Q, K, V);
    }
    // 3) S[h] = scale * Q[h] @ K[h]^T       [16][2048][2048]
    {
        dim3 grid(SEQ / 64, SEQ / 64, NH);
        gemm_nt<<<grid, 256>>>(Q, K, nullptr, S,
                               HD, (size_t)SEQ * HD, (size_t)SEQ * HD,
                               (size_t)SEQ * SEQ, SEQ, ATTN_SCALE);
    }
    // 4) softmax over last dim
    softmax_rows<<<NH * SEQ, 256>>>(S);

    // 5) O[s, h*80+d] = P[h] @ V[h]
    {
        dim3 grid(1, SEQ / 64, NH);
        gemm_pv<<<grid, 256>>>(S, V, O);
    }
    // 6) out = O @ w_proj^T + b_proj       [2048, 1280]
    {
        dim3 grid(DIM / 64, SEQ / 64, 1);
        gemm_nt<<<grid, 256>>>(O, w_proj, b_proj, out,
                               DIM, 0, 0, 0, DIM, 1.0f);
    }
}

// round 5
// speedup vs baseline: 1.4024x; 1.4024x over previous
#include <cuda_runtime.h>
#include <cuda_bf16.h>
#include <math.h>
#include <cstdint>

#define SEQ 2048
#define NH  16
#define HD  80
#define DIM 1280            // NH*HD
#define QKV_N 3840          // 3*DIM
#define ATTN_SCALE 0.11180339887498949f   // 80^-0.5

// ---------------- scratch (device globals; no allocations allowed) ----------
__device__ float g_qkv[SEQ * QKV_N];          // 31.5 MB
__device__ float g_q[NH * SEQ * HD];
__device__ float g_k[NH * SEQ * HD];
__device__ float g_v[NH * SEQ * HD];
__device__ float g_s[(size_t)NH * SEQ * SEQ]; // 256 MB scores
__device__ float g_o[SEQ * DIM];

// bf16 hi/lo splits for tensor-core GEMMs
__device__ __nv_bfloat16 g_hid_hi[SEQ * DIM];
__device__ __nv_bfloat16 g_hid_lo[SEQ * DIM];
__device__ __nv_bfloat16 g_wqkv_hi[QKV_N * DIM];
__device__ __nv_bfloat16 g_wqkv_lo[QKV_N * DIM];
__device__ __nv_bfloat16 g_o_hi[SEQ * DIM];
__device__ __nv_bfloat16 g_o_lo[SEQ * DIM];
__device__ __nv_bfloat16 g_wproj_hi[DIM * DIM];
__device__ __nv_bfloat16 g_wproj_lo[DIM * DIM];

// ================= helpers ====================================================
__device__ __forceinline__ uint32_t smem_u32(const void* p) {
    uint32_t a;
    asm("{ .reg .u64 t; cvta.to.shared.u64 t, %1; cvt.u32.u64 %0, t; }" : "=r"(a) : "l"(p));
    return a;
}
#define CP_ASYNC16(dst, src) \
    asm volatile("cp.async.cg.shared.global [%0], [%1], 16;" :: "r"(dst), "l"(src) : "memory")
#define CP_COMMIT() asm volatile("cp.async.commit_group;" ::: "memory")
#define CP_WAIT1()  asm volatile("cp.async.wait_group 1;" ::: "memory")
#define CP_WAIT0()  asm volatile("cp.async.wait_group 0;" ::: "memory")

#define LDSM_X4(r0, r1, r2, r3, addr) \
    asm volatile("ldmatrix.sync.aligned.m8n8.x4.shared.b16 {%0,%1,%2,%3}, [%4];" \
        : "=r"(r0), "=r"(r1), "=r"(r2), "=r"(r3) : "r"(addr))

#define MMA16816(c, a, b0, b1) \
    asm volatile("mma.sync.aligned.m16n8k16.row.col.f32.bf16.bf16.f32 " \
        "{%0,%1,%2,%3}, {%4,%5,%6,%7}, {%8,%9}, {%0,%1,%2,%3};" \
        : "+f"((c)[0]), "+f"((c)[1]), "+f"((c)[2]), "+f"((c)[3]) \
        : "r"((a)[0]), "r"((a)[1]), "r"((a)[2]), "r"((a)[3]), "r"(b0), "r"(b1))

// ================= fp32 -> bf16 hi/lo split ==================================
__global__ __launch_bounds__(256) void split_bf16(
    const float* __restrict__ x, __nv_bfloat16* __restrict__ hi,
    __nv_bfloat16* __restrict__ lo, int n)
{
    int i = blockIdx.x * blockDim.x + threadIdx.x;
    if (i >= n) return;
    float v = x[i];
    __nv_bfloat16 h = __float2bfloat16(v);
    hi[i] = h;
    lo[i] = __float2bfloat16(v - __bfloat162float(h));
}

// ================= mma.sync bf16x3 NT GEMM ===================================
// C[b] = alpha * A[b](MxK) @ B[b](NxK)^T + bias.  M%128==0, N%128==0, K%32==0.
// A,B as hi/lo bf16 pairs, row-major, leading dim K.
// Tiles: 128x128x32, 8 warps (2x4), warp tile 64x32. cp.async double buffer.
#define MM_TILE_B 10240        // 128 rows * 80 bytes (40 bf16, padded from 32)
#define MM_BUF_B  (4 * MM_TILE_B)
#define MM_SMEM   (2 * MM_BUF_B)   // 81920

__global__ __launch_bounds__(256) void gemm_mma_nt(
    const __nv_bfloat16* __restrict__ Ah, const __nv_bfloat16* __restrict__ Al,
    const __nv_bfloat16* __restrict__ Bh, const __nv_bfloat16* __restrict__ Bl,
    const float* __restrict__ bias, float* __restrict__ C,
    int K, size_t sA, size_t sB, size_t sC, int ldc, float alpha)
{
    extern __shared__ char sm[];
    const uint32_t sbase = smem_u32(sm);
    const int tid = threadIdx.x;
    const int lane = tid & 31;
    const int wid = tid >> 5;
    const int wy = wid >> 2;          // 0..1
    const int wx = wid & 3;           // 0..3
    const int m0 = blockIdx.y * 128;
    const int n0 = blockIdx.x * 128;
    const int bz = blockIdx.z;
    const int NC = K >> 5;

    const __nv_bfloat16* srcs[4] = {Ah + bz * sA, Al + bz * sA,
                                    Bh + bz * sB, Bl + bz * sB};
    const int rb0 = m0, rb1 = n0;

    float acc[4][4][4];
    #pragma unroll
    for (int i = 0; i < 4; i++)
        #pragma unroll
        for (int j = 0; j < 4; j++)
            #pragma unroll
            for (int k = 0; k < 4; k++) acc[i][j][k] = 0.0f;

    // ---- chunk loader: 4 tiles of 128x32 bf16 each, swizzle-free padded rows
    auto load_chunk = [&](int c, int b) {
        const int k0 = c << 5;
        #pragma unroll
        for (int t = 0; t < 4; t++) {
            const __nv_bfloat16* src = srcs[t];
            const int rbase = (t < 2) ? rb0 : rb1;
            const uint32_t tb = sbase + b * MM_BUF_B + t * MM_TILE_B;
            #pragma unroll
            for (int i = 0; i < 2; i++) {
                const int g = tid + i * 256;       // 0..511
                const int row = g >> 2, q = g & 3;
                const uint32_t dst = tb + row * 80 + q * 16;
                const void* s = (const void*)(src + (size_t)(rbase + row) * K + k0 + q * 8);
                CP_ASYNC16(dst, s);
            }
        }
    };

    load_chunk(0, 0);
    CP_COMMIT();

    for (int c = 0; c < NC; c++) {
        if (c + 1 < NC) {
            load_chunk(c + 1, (c + 1) & 1);
            CP_COMMIT();
            CP_WAIT1();
        } else {
            CP_WAIT0();
        }
        __syncthreads();

        const int b = c & 1;
        const uint32_t bufb = sbase + b * MM_BUF_B;
        #pragma unroll
        for (int ks = 0; ks < 2; ks++) {
            const int fcol = ks * 16 + (lane >> 4) * 8;   // k column for ldmatrix
            uint32_t ah[4][4], al[4][4];
            #pragma unroll
            for (int mt = 0; mt < 4; mt++) {
                const int r = wy * 64 + mt * 16 + (lane & 15);
                const uint32_t ad = bufb + r * 80 + fcol * 2;         // Ah tile 0
                LDSM_X4(ah[mt][0], ah[mt][1], ah[mt][2], ah[mt][3], ad);
                const uint32_t ad2 = ad + MM_TILE_B;                  // Al tile 1
                LDSM_X4(al[mt][0], al[mt][1], al[mt][2], al[mt][3], ad2);
            }
            #pragma unroll
            for (int np = 0; np < 2; np++) {
                const int r = wx * 32 + np * 16 + (lane & 15);
                const uint32_t bd = bufb + 2 * MM_TILE_B + r * 80 + fcol * 2; // Bh
                uint32_t h0, h1, h2, h3, l0, l1, l2, l3;
                LDSM_X4(h0, h1, h2, h3, bd);
                LDSM_X4(l0, l1, l2, l3, bd + MM_TILE_B);              // Bl
                #pragma unroll
                for (int mt = 0; mt < 4; mt++) {
                    float* c0 = acc[mt][np * 2];
                    MMA16816(c0, ah[mt], h0, h2);
                    MMA16816(c0, ah[mt], l0, l2);
                    MMA16816(c0, al[mt], h0, h2);
                    float* c1 = acc[mt][np * 2 + 1];
                    MMA16816(c1, ah[mt], h1, h3);
                    MMA16816(c1, ah[mt], l1, l3);
                    MMA16816(c1, al[mt], h1, h3);
                }
            }
        }
        __syncthreads();
    }

    // ---- epilogue ----
    float* Cb = C + bz * sC;
    const int quad = lane >> 2, tq = lane & 3;
    #pragma unroll
    for (int mt = 0; mt < 4; mt++) {
        #pragma unroll
        for (int nt = 0; nt < 4; nt++) {
            const int row = m0 + wy * 64 + mt * 16 + quad;
            const int col = n0 + wx * 32 + nt * 8 + tq * 2;
            float b0 = bias ? bias[col] : 0.0f;
            float b1 = bias ? bias[col + 1] : 0.0f;
            float2 v0 = make_float2(acc[mt][nt][0] * alpha + b0,
                                    acc[mt][nt][1] * alpha + b1);
            float2 v1 = make_float2(acc[mt][nt][2] * alpha + b0,
                                    acc[mt][nt][3] * alpha + b1);
            *reinterpret_cast<float2*>(Cb + (size_t)row * ldc + col) = v0;
            *reinterpret_cast<float2*>(Cb + (size_t)(row + 8) * ldc + col) = v1;
        }
    }
}

// ---------------- generic NT GEMM (FFMA; used for scores) --------------------
__global__ __launch_bounds__(256) void gemm_nt(
    const float* __restrict__ A, const float* __restrict__ B,
    const float* __restrict__ bias, float* __restrict__ C,
    int K, size_t sA, size_t sB, size_t sC, int ldc, float alpha)
{
    __shared__ float As[16][64];
    __shared__ float Bs[16][64];

    const int b = blockIdx.z;
    const float* Ab = A + b * sA;
    const float* Bb = B + b * sB;
    float* Cb = C + b * sC;

    const int m0 = blockIdx.y * 64;
    const int n0 = blockIdx.x * 64;
    const int tid = threadIdx.x;
    const int ty = tid >> 4;
    const int tx = tid & 15;
    const int lrow = tid >> 2;
    const int lk4 = (tid & 3) << 2;

    float acc[4][4] = {};

    for (int k0 = 0; k0 < K; k0 += 16) {
        float4 av = *reinterpret_cast<const float4*>(Ab + (size_t)(m0 + lrow) * K + k0 + lk4);
        As[lk4 + 0][lrow] = av.x; As[lk4 + 1][lrow] = av.y;
        As[lk4 + 2][lrow] = av.z; As[lk4 + 3][lrow] = av.w;
        float4 bv = *reinterpret_cast<const float4*>(Bb + (size_t)(n0 + lrow) * K + k0 + lk4);
        Bs[lk4 + 0][lrow] = bv.x; Bs[lk4 + 1][lrow] = bv.y;
        Bs[lk4 + 2][lrow] = bv.z; Bs[lk4 + 3][lrow] = bv.w;
        __syncthreads();

        #pragma unroll
        for (int k = 0; k < 16; k++) {
            float4 a = *reinterpret_cast<const float4*>(&As[k][ty << 2]);
            float4 bb = *reinterpret_cast<const float4*>(&Bs[k][tx << 2]);
            float ar[4] = {a.x, a.y, a.z, a.w};
            float br[4] = {bb.x, bb.y, bb.z, bb.w};
            #pragma unroll
            for (int i = 0; i < 4; i++)
                #pragma unroll
                for (int j = 0; j < 4; j++)
                    acc[i][j] = fmaf(ar[i], br[j], acc[i][j]);
        }
        __syncthreads();
    }

    #pragma unroll
    for (int i = 0; i < 4; i++) {
        const int row = m0 + (ty << 2) + i;
        #pragma unroll
        for (int j = 0; j < 4; j++) {
            const int col = n0 + (tx << 2) + j;
            float v = acc[i][j] * alpha;
            if (bias) v += bias[col];
            Cb[(size_t)row * ldc + col] = v;
        }
    }
}

// ---------------- RoPE + split to per-head layout ---------------------------
__global__ __launch_bounds__(256) void rope_split(
    const float* __restrict__ qkv, const float* __restrict__ cosp,
    const float* __restrict__ sinp,
    float* __restrict__ Q, float* __restrict__ Kb, float* __restrict__ V)
{
    int idx = blockIdx.x * blockDim.x + threadIdx.x;
    if (idx >= SEQ * DIM) return;
    const int d = idx % HD;
    const int h = (idx / HD) % NH;
    const int s = idx / DIM;

    const float c = cosp[s * HD + d];
    const float sn = sinp[s * HD + d];
    const int d2 = (d < HD / 2) ? d + HD / 2 : d - HD / 2;
    const float sign = (d < HD / 2) ? -1.0f : 1.0f;

    const size_t rowbase = (size_t)s * QKV_N + h * HD;
    const size_t out = ((size_t)h * SEQ + s) * HD + d;

    const float qv = qkv[rowbase + d];
    const float q2 = qkv[rowbase + d2];
    Q[out] = fmaf(qv, c, sign * q2 * sn);

    const float kv = qkv[rowbase + DIM + d];
    const float k2 = qkv[rowbase + DIM + d2];
    Kb[out] = fmaf(kv, c, sign * k2 * sn);

    V[out] = qkv[rowbase + 2 * DIM + d];
}

// ---------------- row softmax ------------------------------------------------
__global__ __launch_bounds__(256) void softmax_rows(float* __restrict__ S)
{
    float* row = S + (size_t)blockIdx.x * SEQ;
    const int tid = threadIdx.x;
    __shared__ float red[256];

    float v[8];
    float mx = -1e30f;
    #pragma unroll
    for (int i = 0; i < 8; i++) {
        v[i] = row[tid + i * 256];
        mx = fmaxf(mx, v[i]);
    }
    red[tid] = mx;
    __syncthreads();
    for (int s = 128; s > 0; s >>= 1) {
        if (tid < s) red[tid] = fmaxf(red[tid], red[tid + s]);
        __syncthreads();
    }
    mx = red[0];
    __syncthreads();

    float sum = 0.0f;
    #pragma unroll
    for (int i = 0; i < 8; i++) {
        v[i] = __expf(v[i] - mx);
        sum += v[i];
    }
    red[tid] = sum;
    __syncthreads();
    for (int s = 128; s > 0; s >>= 1) {
        if (tid < s) red[tid] += red[tid + s];
        __syncthreads();
    }
    const float inv = 1.0f / red[0];
    #pragma unroll
    for (int i = 0; i < 8; i++) row[tid + i * 256] = v[i] * inv;
}

// ---------------- NN GEMM: O_h[s,d] = sum_t P_h[s,t] * V_h[t,d] -------------
__global__ __launch_bounds__(256) void gemm_pv(
    const float* __restrict__ P, const float* __restrict__ V,
    float* __restrict__ O)
{
    __shared__ float Ps[16][64];
    __shared__ float Vs[16][80];

    const int h = blockIdx.z;
    const float* Pb = P + (size_t)h * SEQ * SEQ;
    const float* Vb = V + (size_t)h * SEQ * HD;

    const int m0 = blockIdx.y * 64;
    const int tid = threadIdx.x;
    const int ty = tid >> 4;
    const int tx = tid & 15;

    const int lrow = tid >> 2;
    const int lk4 = (tid & 3) << 2;
    const int vkk = tid >> 4;
    const int vc5 = (tid & 15) * 5;

    float acc[4][5] = {};

    for (int k0 = 0; k0 < SEQ; k0 += 16) {
        float4 pv = *reinterpret_cast<const float4*>(Pb + (size_t)(m0 + lrow) * SEQ + k0 + lk4);
        Ps[lk4 + 0][lrow] = pv.x; Ps[lk4 + 1][lrow] = pv.y;
        Ps[lk4 + 2][lrow] = pv.z; Ps[lk4 + 3][lrow] = pv.w;
        #pragma unroll
        for (int j = 0; j < 5; j++)
            Vs[vkk][vc5 + j] = Vb[(size_t)(k0 + vkk) * HD + vc5 + j];
        __syncthreads();

        #pragma unroll
        for (int k = 0; k < 16; k++) {
            float4 a = *reinterpret_cast<const float4*>(&Ps[k][ty << 2]);
            float ar[4] = {a.x, a.y, a.z, a.w};
            float br[5];
            #pragma unroll
            for (int j = 0; j < 5; j++) br[j] = Vs[k][tx * 5 + j];
            #pragma unroll
            for (int i = 0; i < 4; i++)
                #pragma unroll
                for (int j = 0; j < 5; j++)
                    acc[i][j] = fmaf(ar[i], br[j], acc[i][j]);
        }
        __syncthreads();
    }

    #pragma unroll
    for (int i = 0; i < 4; i++) {
        const int row = m0 + (ty << 2) + i;
        #pragma unroll
        for (int j = 0; j < 5; j++) {
            const int col = h * HD + tx * 5 + j;
            O[(size_t)row * DIM + col] = acc[i][j];
        }
    }
}

// ---------------- launch -----------------------------------------------------
extern "C" void kernel_launch(void* const* d_in, const int* in_sizes, int n_in,
                              void* d_out, int out_size)
{
    const float* hidden = (const float*)d_in[0];
    const float* cosp   = (const float*)d_in[2];
    const float* sinp   = (const float*)d_in[3];
    const float* w_qkv  = (const float*)d_in[4];
    const float* b_qkv  = (const float*)d_in[5];
    const float* w_proj = (const float*)d_in[6];
    const float* b_proj = (const float*)d_in[7];
    float* out = (float*)d_out;

    float *qkv, *Q, *K, *V, *S, *O;
    cudaGetSymbolAddress((void**)&qkv, g_qkv);
    cudaGetSymbolAddress((void**)&Q, g_q);
    cudaGetSymbolAddress((void**)&K, g_k);
    cudaGetSymbolAddress((void**)&V, g_v);
    cudaGetSymbolAddress((void**)&S, g_s);
    cudaGetSymbolAddress((void**)&O, g_o);

    __nv_bfloat16 *hh, *hl, *wh, *wl, *oh, *ol, *ph, *pl;
    cudaGetSymbolAddress((void**)&hh, g_hid_hi);
    cudaGetSymbolAddress((void**)&hl, g_hid_lo);
    cudaGetSymbolAddress((void**)&wh, g_wqkv_hi);
    cudaGetSymbolAddress((void**)&wl, g_wqkv_lo);
    cudaGetSymbolAddress((void**)&oh, g_o_hi);
    cudaGetSymbolAddress((void**)&ol, g_o_lo);
    cudaGetSymbolAddress((void**)&ph, g_wproj_hi);
    cudaGetSymbolAddress((void**)&pl, g_wproj_lo);

    cudaFuncSetAttribute(gemm_mma_nt, cudaFuncAttributeMaxDynamicSharedMemorySize,
                         MM_SMEM);

    // 0) split inputs for tensor-core GEMMs
    split_bf16<<<(SEQ * DIM + 255) / 256, 256>>>(hidden, hh, hl, SEQ * DIM);
    split_bf16<<<(QKV_N * DIM + 255) / 256, 256>>>(w_qkv, wh, wl, QKV_N * DIM);
    split_bf16<<<(DIM * DIM + 255) / 256, 256>>>(w_proj, ph, pl, DIM * DIM);

    // 1) QKV = hidden @ w_qkv^T + b_qkv  (mma.sync bf16x3)
    {
        dim3 grid(QKV_N / 128, SEQ / 128, 1);
        gemm_mma_nt<<<grid, 256, MM_SMEM>>>(hh, hl, wh, wl, b_qkv, qkv,
                                            DIM, 0, 0, 0, QKV_N, 1.0f);
    }
    // 2) RoPE + split into per-head Q,K,V  [h][s][d]
    rope_split<<<(SEQ * DIM + 255) / 256, 256>>>(qkv, cosp, sinp, Q, K, V);

    // 3) S[h] = scale * Q[h] @ K[h]^T   (FFMA)
    {
        dim3 grid(SEQ / 64, SEQ / 64, NH);
        gemm_nt<<<grid, 256>>>(Q, K, nullptr, S,
                               HD, (size_t)SEQ * HD, (size_t)SEQ * HD,
                               (size_t)SEQ * SEQ, SEQ, ATTN_SCALE);
    }
    // 4) softmax
    softmax_rows<<<NH * SEQ, 256>>>(S);

    // 5) O = P @ V   (FFMA)
    {
        dim3 grid(1, SEQ / 64, NH);
        gemm_pv<<<grid, 256>>>(S, V, O);
    }
    // 6) out = O @ w_proj^T + b_proj  (mma.sync bf16x3)
    split_bf16<<<(SEQ * DIM + 255) / 256, 256>>>(O, oh, ol, SEQ * DIM);
    {
        dim3 grid(DIM / 128, SEQ / 128, 1);
        gemm_mma_nt<<<grid, 256, MM_SMEM>>>(oh, ol, ph, pl, b_proj, out,
                                            DIM, 0, 0, 0, DIM, 1.0f);
    }
}

// round 6
// speedup vs baseline: 1.9569x; 1.3954x over previous
#include <cuda_runtime.h>
#include <cuda_bf16.h>
#include <math.h>
#include <cstdint>

#define SEQ 2048
#define NH  16
#define HD  80
#define HDP 96              // padded head dim for Q/K (K chunks of 32)
#define HDV 128             // padded head dim for V^T (one 128-col N tile)
#define DIM 1280            // NH*HD
#define QKV_N 3840          // 3*DIM
#define ATTN_SCALE 0.11180339887498949f   // 80^-0.5

// ---------------- scratch (device globals; no allocations allowed) ----------
__device__ float g_qkv[SEQ * QKV_N];          // 31.5 MB
__device__ float g_s[(size_t)NH * SEQ * SEQ]; // 256 MB scores
__device__ float g_o[SEQ * DIM];

__device__ __nv_bfloat16 g_qh[NH * SEQ * HDP];
__device__ __nv_bfloat16 g_ql[NH * SEQ * HDP];
__device__ __nv_bfloat16 g_kh[NH * SEQ * HDP];
__device__ __nv_bfloat16 g_kl[NH * SEQ * HDP];
__device__ __nv_bfloat16 g_vth[NH * HDV * SEQ];   // V^T padded
__device__ __nv_bfloat16 g_vtl[NH * HDV * SEQ];
__device__ __nv_bfloat16 g_ph[(size_t)NH * SEQ * SEQ];  // 128 MB
__device__ __nv_bfloat16 g_pl[(size_t)NH * SEQ * SEQ];

__device__ __nv_bfloat16 g_hid_hi[SEQ * DIM];
__device__ __nv_bfloat16 g_hid_lo[SEQ * DIM];
__device__ __nv_bfloat16 g_wqkv_hi[QKV_N * DIM];
__device__ __nv_bfloat16 g_wqkv_lo[QKV_N * DIM];
__device__ __nv_bfloat16 g_o_hi[SEQ * DIM];
__device__ __nv_bfloat16 g_o_lo[SEQ * DIM];
__device__ __nv_bfloat16 g_wproj_hi[DIM * DIM];
__device__ __nv_bfloat16 g_wproj_lo[DIM * DIM];

// ================= helpers ====================================================
__device__ __forceinline__ uint32_t smem_u32(const void* p) {
    uint32_t a;
    asm("{ .reg .u64 t; cvta.to.shared.u64 t, %1; cvt.u32.u64 %0, t; }" : "=r"(a) : "l"(p));
    return a;
}
#define CP_ASYNC16(dst, src) \
    asm volatile("cp.async.cg.shared.global [%0], [%1], 16;" :: "r"(dst), "l"(src) : "memory")
#define CP_COMMIT() asm volatile("cp.async.commit_group;" ::: "memory")
#define CP_WAIT1()  asm volatile("cp.async.wait_group 1;" ::: "memory")
#define CP_WAIT0()  asm volatile("cp.async.wait_group 0;" ::: "memory")

#define LDSM_X4(r0, r1, r2, r3, addr) \
    asm volatile("ldmatrix.sync.aligned.m8n8.x4.shared.b16 {%0,%1,%2,%3}, [%4];" \
        : "=r"(r0), "=r"(r1), "=r"(r2), "=r"(r3) : "r"(addr))

#define MMA16816(c, a, b0, b1) \
    asm volatile("mma.sync.aligned.m16n8k16.row.col.f32.bf16.bf16.f32 " \
        "{%0,%1,%2,%3}, {%4,%5,%6,%7}, {%8,%9}, {%0,%1,%2,%3};" \
        : "+f"((c)[0]), "+f"((c)[1]), "+f"((c)[2]), "+f"((c)[3]) \
        : "r"((a)[0]), "r"((a)[1]), "r"((a)[2]), "r"((a)[3]), "r"(b0), "r"(b1))

__device__ __forceinline__ void split1(float v, __nv_bfloat16& h, __nv_bfloat16& l) {
    h = __float2bfloat16(v);
    l = __float2bfloat16(v - __bfloat162float(h));
}

// ================= fp32 -> bf16 hi/lo split ==================================
__global__ __launch_bounds__(256) void split_bf16(
    const float* __restrict__ x, __nv_bfloat16* __restrict__ hi,
    __nv_bfloat16* __restrict__ lo, int n)
{
    int i = blockIdx.x * blockDim.x + threadIdx.x;
    if (i >= n) return;
    float v = x[i];
    __nv_bfloat16 h = __float2bfloat16(v);
    hi[i] = h;
    lo[i] = __float2bfloat16(v - __bfloat162float(h));
}

// ================= mma.sync bf16x3 NT GEMM ===================================
// C (+bz*sC offset)[m, n] = alpha * sum_k A[bz][m,k]*B[bz][n,k] + bias[n],
// cols written only when n < n_valid.  M%128==0, (N tile)=128, K%32==0.
#define MM_TILE_B 10240        // 128 rows * 80 bytes (40 bf16, padded from 32)
#define MM_BUF_B  (4 * MM_TILE_B)
#define MM_SMEM   (2 * MM_BUF_B)   // 81920

__global__ __launch_bounds__(256) void gemm_mma_nt(
    const __nv_bfloat16* __restrict__ Ah, const __nv_bfloat16* __restrict__ Al,
    const __nv_bfloat16* __restrict__ Bh, const __nv_bfloat16* __restrict__ Bl,
    const float* __restrict__ bias, float* __restrict__ C,
    int K, size_t sA, size_t sB, size_t sC, int ldc, float alpha, int n_valid)
{
    extern __shared__ char sm[];
    const uint32_t sbase = smem_u32(sm);
    const int tid = threadIdx.x;
    const int lane = tid & 31;
    const int wid = tid >> 5;
    const int wy = wid >> 2;          // 0..1
    const int wx = wid & 3;           // 0..3
    const int m0 = blockIdx.y * 128;
    const int n0 = blockIdx.x * 128;
    const int bz = blockIdx.z;
    const int NC = K >> 5;

    const __nv_bfloat16* srcs[4] = {Ah + bz * sA, Al + bz * sA,
                                    Bh + bz * sB, Bl + bz * sB};
    const int rb0 = m0, rb1 = n0;

    float acc[4][4][4];
    #pragma unroll
    for (int i = 0; i < 4; i++)
        #pragma unroll
        for (int j = 0; j < 4; j++)
            #pragma unroll
            for (int k = 0; k < 4; k++) acc[i][j][k] = 0.0f;

    auto load_chunk = [&](int c, int b) {
        const int k0 = c << 5;
        #pragma unroll
        for (int t = 0; t < 4; t++) {
            const __nv_bfloat16* src = srcs[t];
            const int rbase = (t < 2) ? rb0 : rb1;
            const uint32_t tb = sbase + b * MM_BUF_B + t * MM_TILE_B;
            #pragma unroll
            for (int i = 0; i < 2; i++) {
                const int g = tid + i * 256;       // 0..511
                const int row = g >> 2, q = g & 3;
                const uint32_t dst = tb + row * 80 + q * 16;
                const void* s = (const void*)(src + (size_t)(rbase + row) * K + k0 + q * 8);
                CP_ASYNC16(dst, s);
            }
        }
    };

    load_chunk(0, 0);
    CP_COMMIT();

    for (int c = 0; c < NC; c++) {
        if (c + 1 < NC) {
            load_chunk(c + 1, (c + 1) & 1);
            CP_COMMIT();
            CP_WAIT1();
        } else {
            CP_WAIT0();
        }
        __syncthreads();

        const int b = c & 1;
        const uint32_t bufb = sbase + b * MM_BUF_B;
        #pragma unroll
        for (int ks = 0; ks < 2; ks++) {
            const int fcol = ks * 16 + (lane >> 4) * 8;
            uint32_t bh[2][4], bl[2][4];
            #pragma unroll
            for (int np = 0; np < 2; np++) {
                const int r = wx * 32 + np * 16 + (lane & 15);
                const uint32_t bd = bufb + 2 * MM_TILE_B + r * 80 + fcol * 2;
                LDSM_X4(bh[np][0], bh[np][1], bh[np][2], bh[np][3], bd);
                LDSM_X4(bl[np][0], bl[np][1], bl[np][2], bl[np][3], bd + MM_TILE_B);
            }
            #pragma unroll
            for (int mt = 0; mt < 4; mt++) {
                const int r = wy * 64 + mt * 16 + (lane & 15);
                const uint32_t ad = bufb + r * 80 + fcol * 2;
                uint32_t ah[4], al[4];
                LDSM_X4(ah[0], ah[1], ah[2], ah[3], ad);
                LDSM_X4(al[0], al[1], al[2], al[3], ad + MM_TILE_B);
                // variant-major ordering: each acc reused at distance 4 MMAs
                #pragma unroll
                for (int np = 0; np < 2; np++) {
                    MMA16816(acc[mt][np * 2],     ah, bh[np][0], bh[np][2]);
                    MMA16816(acc[mt][np * 2 + 1], ah, bh[np][1], bh[np][3]);
                }
                #pragma unroll
                for (int np = 0; np < 2; np++) {
                    MMA16816(acc[mt][np * 2],     ah, bl[np][0], bl[np][2]);
                    MMA16816(acc[mt][np * 2 + 1], ah, bl[np][1], bl[np][3]);
                }
                #pragma unroll
                for (int np = 0; np < 2; np++) {
                    MMA16816(acc[mt][np * 2],     al, bh[np][0], bh[np][2]);
                    MMA16816(acc[mt][np * 2 + 1], al, bh[np][1], bh[np][3]);
                }
            }
        }
        __syncthreads();
    }

    // ---- epilogue ----
    float* Cb = C + bz * sC;
    const int quad = lane >> 2, tq = lane & 3;
    #pragma unroll
    for (int mt = 0; mt < 4; mt++) {
        #pragma unroll
        for (int nt = 0; nt < 4; nt++) {
            const int col = n0 + wx * 32 + nt * 8 + tq * 2;
            if (col >= n_valid) continue;
            const int row = m0 + wy * 64 + mt * 16 + quad;
            float b0 = bias ? bias[col] : 0.0f;
            float b1 = bias ? bias[col + 1] : 0.0f;
            float2 v0 = make_float2(acc[mt][nt][0] * alpha + b0,
                                    acc[mt][nt][1] * alpha + b1);
            float2 v1 = make_float2(acc[mt][nt][2] * alpha + b0,
                                    acc[mt][nt][3] * alpha + b1);
            *reinterpret_cast<float2*>(Cb + (size_t)row * ldc + col) = v0;
            *reinterpret_cast<float2*>(Cb + (size_t)(row + 8) * ldc + col) = v1;
        }
    }
}

// ---------------- RoPE + split to bf16 hi/lo per-head layouts ---------------
// Q,K: [h][s][HDP] (cols 80..95 zeroed by pad kernel). V^T: [h][d][s].
__global__ __launch_bounds__(256) void rope_split_bf16(
    const float* __restrict__ qkv, const float* __restrict__ cosp,
    const float* __restrict__ sinp,
    __nv_bfloat16* __restrict__ Qh, __nv_bfloat16* __restrict__ Ql,
    __nv_bfloat16* __restrict__ Kh, __nv_bfloat16* __restrict__ Kl,
    __nv_bfloat16* __restrict__ Vth, __nv_bfloat16* __restrict__ Vtl)
{
    int idx = blockIdx.x * blockDim.x + threadIdx.x;
    if (idx >= SEQ * DIM) return;
    const int d = idx % HD;
    const int h = (idx / HD) % NH;
    const int s = idx / DIM;

    const float c = cosp[s * HD + d];
    const float sn = sinp[s * HD + d];
    const int d2 = (d < HD / 2) ? d + HD / 2 : d - HD / 2;
    const float sign = (d < HD / 2) ? -1.0f : 1.0f;

    const size_t rowbase = (size_t)s * QKV_N + h * HD;
    const size_t oqk = ((size_t)h * SEQ + s) * HDP + d;
    const size_t ovt = ((size_t)h * HDV + d) * SEQ + s;

    const float qv = qkv[rowbase + d];
    const float q2 = qkv[rowbase + d2];
    float qr = fmaf(qv, c, sign * q2 * sn);
    split1(qr, Qh[oqk], Ql[oqk]);

    const float kv = qkv[rowbase + DIM + d];
    const float k2 = qkv[rowbase + DIM + d2];
    float kr = fmaf(kv, c, sign * k2 * sn);
    split1(kr, Kh[oqk], Kl[oqk]);

    split1(qkv[rowbase + 2 * DIM + d], Vth[ovt], Vtl[ovt]);
}

// ---------------- zero-fill pad regions (deterministic, every launch) -------
__global__ __launch_bounds__(256) void pad_qk(
    __nv_bfloat16* __restrict__ Qh, __nv_bfloat16* __restrict__ Ql,
    __nv_bfloat16* __restrict__ Kh, __nv_bfloat16* __restrict__ Kl)
{
    int i = blockIdx.x * blockDim.x + threadIdx.x;      // NH*SEQ*16
    if (i >= NH * SEQ * 16) return;
    const int d = HD + (i & 15);
    const int row = i >> 4;                              // h*SEQ + s
    const size_t o = (size_t)row * HDP + d;
    Qh[o] = __nv_bfloat16(0.0f); Ql[o] = __nv_bfloat16(0.0f);
    Kh[o] = __nv_bfloat16(0.0f); Kl[o] = __nv_bfloat16(0.0f);
}
__global__ __launch_bounds__(256) void pad_vt(
    __nv_bfloat16* __restrict__ Vth, __nv_bfloat16* __restrict__ Vtl)
{
    int i = blockIdx.x * blockDim.x + threadIdx.x;      // NH*48*SEQ
    if (i >= NH * (HDV - HD) * SEQ) return;
    const int s = i % SEQ;
    const int r = (i / SEQ) % (HDV - HD);
    const int h = i / (SEQ * (HDV - HD));
    const size_t o = ((size_t)h * HDV + HD + r) * SEQ + s;
    Vth[o] = __nv_bfloat16(0.0f); Vtl[o] = __nv_bfloat16(0.0f);
}

// ---------------- row softmax, fused bf16 hi/lo split ------------------------
__global__ __launch_bounds__(256) void softmax_split(
    const float* __restrict__ S, __nv_bfloat16* __restrict__ Ph,
    __nv_bfloat16* __restrict__ Pl)
{
    const size_t base = (size_t)blockIdx.x * SEQ;
    const float* row = S + base;
    const int tid = threadIdx.x;
    __shared__ float red[256];

    float v[8];
    float mx = -1e30f;
    #pragma unroll
    for (int i = 0; i < 8; i++) {
        v[i] = row[tid + i * 256];
        mx = fmaxf(mx, v[i]);
    }
    red[tid] = mx;
    __syncthreads();
    for (int s = 128; s > 0; s >>= 1) {
        if (tid < s) red[tid] = fmaxf(red[tid], red[tid + s]);
        __syncthreads();
    }
    mx = red[0];
    __syncthreads();

    float sum = 0.0f;
    #pragma unroll
    for (int i = 0; i < 8; i++) {
        v[i] = __expf(v[i] - mx);
        sum += v[i];
    }
    red[tid] = sum;
    __syncthreads();
    for (int s = 128; s > 0; s >>= 1) {
        if (tid < s) red[tid] += red[tid + s];
        __syncthreads();
    }
    const float inv = 1.0f / red[0];
    #pragma unroll
    for (int i = 0; i < 8; i++) {
        float p = v[i] * inv;
        __nv_bfloat16 h, l;
        split1(p, h, l);
        Ph[base + tid + i * 256] = h;
        Pl[base + tid + i * 256] = l;
    }
}

// ---------------- launch -----------------------------------------------------
extern "C" void kernel_launch(void* const* d_in, const int* in_sizes, int n_in,
                              void* d_out, int out_size)
{
    const float* hidden = (const float*)d_in[0];
    const float* cosp   = (const float*)d_in[2];
    const float* sinp   = (const float*)d_in[3];
    const float* w_qkv  = (const float*)d_in[4];
    const float* b_qkv  = (const float*)d_in[5];
    const float* w_proj = (const float*)d_in[6];
    const float* b_proj = (const float*)d_in[7];
    float* out = (float*)d_out;

    float *qkv, *S, *O;
    cudaGetSymbolAddress((void**)&qkv, g_qkv);
    cudaGetSymbolAddress((void**)&S, g_s);
    cudaGetSymbolAddress((void**)&O, g_o);

    __nv_bfloat16 *hh, *hl, *wh, *wl, *oh, *ol, *prh, *prl;
    __nv_bfloat16 *qh, *ql, *kh, *kl, *vth, *vtl, *ph, *pl;
    cudaGetSymbolAddress((void**)&hh, g_hid_hi);
    cudaGetSymbolAddress((void**)&hl, g_hid_lo);
    cudaGetSymbolAddress((void**)&wh, g_wqkv_hi);
    cudaGetSymbolAddress((void**)&wl, g_wqkv_lo);
    cudaGetSymbolAddress((void**)&oh, g_o_hi);
    cudaGetSymbolAddress((void**)&ol, g_o_lo);
    cudaGetSymbolAddress((void**)&prh, g_wproj_hi);
    cudaGetSymbolAddress((void**)&prl, g_wproj_lo);
    cudaGetSymbolAddress((void**)&qh, g_qh);
    cudaGetSymbolAddress((void**)&ql, g_ql);
    cudaGetSymbolAddress((void**)&kh, g_kh);
    cudaGetSymbolAddress((void**)&kl, g_kl);
    cudaGetSymbolAddress((void**)&vth, g_vth);
    cudaGetSymbolAddress((void**)&vtl, g_vtl);
    cudaGetSymbolAddress((void**)&ph, g_ph);
    cudaGetSymbolAddress((void**)&pl, g_pl);

    cudaFuncSetAttribute(gemm_mma_nt, cudaFuncAttributeMaxDynamicSharedMemorySize,
                         MM_SMEM);

    // 0) split inputs
    split_bf16<<<(SEQ * DIM + 255) / 256, 256>>>(hidden, hh, hl, SEQ * DIM);
    split_bf16<<<(QKV_N * DIM + 255) / 256, 256>>>(w_qkv, wh, wl, QKV_N * DIM);
    split_bf16<<<(DIM * DIM + 255) / 256, 256>>>(w_proj, prh, prl, DIM * DIM);

    // 1) QKV = hidden @ w_qkv^T + b_qkv
    {
        dim3 grid(QKV_N / 128, SEQ / 128, 1);
        gemm_mma_nt<<<grid, 256, MM_SMEM>>>(hh, hl, wh, wl, b_qkv, qkv,
                                            DIM, 0, 0, 0, QKV_N, 1.0f, QKV_N);
    }
    // 2) RoPE + per-head bf16 layouts (+ pad zeros)
    pad_qk<<<(NH * SEQ * 16 + 255) / 256, 256>>>(qh, ql, kh, kl);
    pad_vt<<<(NH * (HDV - HD) * SEQ + 255) / 256, 256>>>(vth, vtl);
    rope_split_bf16<<<(SEQ * DIM + 255) / 256, 256>>>(qkv, cosp, sinp,
                                                      qh, ql, kh, kl, vth, vtl);

    // 3) S[h] = scale * Q[h] @ K[h]^T   (mma, K=96)
    {
        dim3 grid(SEQ / 128, SEQ / 128, NH);
        gemm_mma_nt<<<grid, 256, MM_SMEM>>>(qh, ql, kh, kl, nullptr, S,
                                            HDP, (size_t)SEQ * HDP, (size_t)SEQ * HDP,
                                            (size_t)SEQ * SEQ, SEQ, ATTN_SCALE, SEQ);
    }
    // 4) softmax + split P to bf16 hi/lo
    softmax_split<<<NH * SEQ, 256>>>(S, ph, pl);

    // 5) O[s, h*80+d] = P[h] @ V[h]  (mma: A=P, B=V^T, N=128 padded, 80 valid)
    {
        dim3 grid(1, SEQ / 128, NH);
        gemm_mma_nt<<<grid, 256, MM_SMEM>>>(ph, pl, vth, vtl, nullptr, O,
                                            SEQ, (size_t)SEQ * SEQ, (size_t)HDV * SEQ,
                                            (size_t)HD, DIM, 1.0f, HD);
    }
    // 6) out = O @ w_proj^T + b_proj
    split_bf16<<<(SEQ * DIM + 255) / 256, 256>>>(O, oh, ol, SEQ * DIM);
    {
        dim3 grid(DIM / 128, SEQ / 128, 1);
        gemm_mma_nt<<<grid, 256, MM_SMEM>>>(oh, ol, prh, prl, b_proj, out,
                                            DIM, 0, 0, 0, DIM, 1.0f, DIM);
    }
}